// round 1
// baseline (speedup 1.0000x reference)
#include <cuda_runtime.h>
#include <math.h>

#define Bsz 2
#define Nn 2048
#define Cc 256
#define COOR 3
#define Hh 8
#define Dd 64
#define Ee 192   // Dd * COOR
#define DI 512   // Hh * Dd

// Scratch (device globals — no runtime allocation allowed)
__device__ float g_q[Bsz*Hh*Nn*Ee];
__device__ float g_k[Bsz*Hh*Nn*Ee];
__device__ float g_v[Bsz*Hh*Nn*Ee];
__device__ float g_ao[Bsz*Hh*Nn*Ee];
__device__ float g_sim[Bsz*Hh*Nn*Nn];   // 256 MiB

// ---------------------------------------------------------------------------
// Projection kernel.
// MODE 0: q/k/v projection.  in = x (B,N,C,3), W = (512,256),
//         out[b][h][n][d*3+c] = sum_i x[b][n][i][c] * W[h*64+d][i]
// MODE 1: output projection. in = g_ao (B,H,N,192), W = Wo (256,512),
//         out[b][n][o][c]    = sum_i2 ao[b][i2/64][n][(i2%64)*3+c] * W[o][i2]
// Block: 64 outputs (o) x 16 rows (n), 256 threads, k-tiles of 64.
// ---------------------------------------------------------------------------
template<int MODE>
__global__ __launch_bounds__(256)
void vn_proj(const float* __restrict__ in, const float* __restrict__ W,
             float* __restrict__ out)
{
    constexpr int K  = (MODE == 0) ? Cc : DI;
    constexpr int NT = K / 64;

    __shared__ float Wt[64][68];   // [kk][o_local], padded
    __shared__ float Xt[16][Ee];   // [n_local][i_local*3 + c]

    const int tid   = threadIdx.x;
    const int o0    = blockIdx.x * 64;
    const int ntile = blockIdx.y % (Nn / 16);
    const int b     = blockIdx.y / (Nn / 16);
    const int n0    = ntile * 16;
    const int n_loc = tid >> 4;    // 0..15
    const int o_grp = tid & 15;    // 0..15 -> o_local = o_grp*4 + u

    float acc[4][3] = {};

    for (int t = 0; t < NT; ++t) {
        const int k0 = t * 64;

        // Load Xt: 16 rows x 192 contiguous floats, coalesced.
        #pragma unroll
        for (int j = 0; j < 12; ++j) {
            int l   = tid + j * 256;
            int nl  = l / Ee;
            int idx = l - nl * Ee;
            long base;
            if (MODE == 0)
                base = (((long)b * Nn + (n0 + nl)) * Cc + k0) * COOR;
            else
                base = (((long)b * Hh + t) * Nn + (n0 + nl)) * (long)Ee;
            Xt[nl][idx] = in[base + idx];
        }
        // Load Wt: 64 o x 64 k, coalesced along k, stored [kk][o].
        #pragma unroll
        for (int j = 0; j < 16; ++j) {
            int l  = tid + j * 256;
            int kk = l & 63;
            int o  = l >> 6;
            Wt[kk][o] = W[(long)(o0 + o) * K + k0 + kk];
        }
        __syncthreads();

        #pragma unroll
        for (int kk = 0; kk < 64; ++kk) {
            float x0 = Xt[n_loc][kk*3 + 0];
            float x1 = Xt[n_loc][kk*3 + 1];
            float x2 = Xt[n_loc][kk*3 + 2];
            float4 w = *(const float4*)&Wt[kk][o_grp * 4];
            acc[0][0] += w.x * x0; acc[0][1] += w.x * x1; acc[0][2] += w.x * x2;
            acc[1][0] += w.y * x0; acc[1][1] += w.y * x1; acc[1][2] += w.y * x2;
            acc[2][0] += w.z * x0; acc[2][1] += w.z * x1; acc[2][2] += w.z * x2;
            acc[3][0] += w.w * x0; acc[3][1] += w.w * x1; acc[3][2] += w.w * x2;
        }
        __syncthreads();
    }

    const int n = n0 + n_loc;
    #pragma unroll
    for (int u = 0; u < 4; ++u) {
        int o = o0 + o_grp * 4 + u;
        if (MODE == 0) {
            int h = o >> 6, d = o & 63;
            float* dst = &out[(((long)b * Hh + h) * Nn + n) * (long)Ee + d * 3];
            dst[0] = acc[u][0]; dst[1] = acc[u][1]; dst[2] = acc[u][2];
        } else {
            float* dst = &out[(((long)b * Nn + n) * Cc + o) * (long)COOR];
            dst[0] = acc[u][0]; dst[1] = acc[u][1]; dst[2] = acc[u][2];
        }
    }
}

// ---------------------------------------------------------------------------
// Batched tiled GEMM: C[i][j] = alpha * sum_k A[i][k] * B(k,j)
// BT=true : B given row-major [j][k] (ldb along k)  -> QK^T
// BT=false: B given row-major [k][j] (ldb along j)  -> attn @ V
// BM=BN=64, BK=32, 256 threads, 4x4 register tile.
// ---------------------------------------------------------------------------
template<bool BT>
__global__ __launch_bounds__(256)
void gemm_tile(const float* __restrict__ A, const float* __restrict__ Bm,
               float* __restrict__ Cm, int Kdim, int lda, int ldb, int ldc,
               long strideA, long strideB, long strideC, float alpha)
{
    __shared__ float As[32][68];
    __shared__ float Bs[32][68];

    const int tid = threadIdx.x;
    const int bh  = blockIdx.z;
    A  += (long)bh * strideA;
    Bm += (long)bh * strideB;
    Cm += (long)bh * strideC;

    const int j0 = blockIdx.x * 64;
    const int i0 = blockIdx.y * 64;
    const int tx = tid & 15;   // col group
    const int ty = tid >> 4;   // row group

    float acc[4][4] = {};

    for (int k0 = 0; k0 < Kdim; k0 += 32) {
        #pragma unroll
        for (int j = 0; j < 8; ++j) {
            int l  = tid + j * 256;
            int kk = l & 31, m = l >> 5;
            As[kk][m] = A[(long)(i0 + m) * lda + k0 + kk];
        }
        if (BT) {
            #pragma unroll
            for (int j = 0; j < 8; ++j) {
                int l  = tid + j * 256;
                int kk = l & 31, nn = l >> 5;
                Bs[kk][nn] = Bm[(long)(j0 + nn) * ldb + k0 + kk];
            }
        } else {
            #pragma unroll
            for (int j = 0; j < 8; ++j) {
                int l  = tid + j * 256;
                int nn = l & 63, kk = l >> 6;
                Bs[kk][nn] = Bm[(long)(k0 + kk) * ldb + j0 + nn];
            }
        }
        __syncthreads();

        #pragma unroll
        for (int kk = 0; kk < 32; ++kk) {
            float4 a  = *(const float4*)&As[kk][ty * 4];
            float4 bb = *(const float4*)&Bs[kk][tx * 4];
            acc[0][0] += a.x * bb.x; acc[0][1] += a.x * bb.y;
            acc[0][2] += a.x * bb.z; acc[0][3] += a.x * bb.w;
            acc[1][0] += a.y * bb.x; acc[1][1] += a.y * bb.y;
            acc[1][2] += a.y * bb.z; acc[1][3] += a.y * bb.w;
            acc[2][0] += a.z * bb.x; acc[2][1] += a.z * bb.y;
            acc[2][2] += a.z * bb.z; acc[2][3] += a.z * bb.w;
            acc[3][0] += a.w * bb.x; acc[3][1] += a.w * bb.y;
            acc[3][2] += a.w * bb.z; acc[3][3] += a.w * bb.w;
        }
        __syncthreads();
    }

    #pragma unroll
    for (int u = 0; u < 4; ++u) {
        float4 r;
        r.x = acc[u][0] * alpha; r.y = acc[u][1] * alpha;
        r.z = acc[u][2] * alpha; r.w = acc[u][3] * alpha;
        *(float4*)&Cm[(long)(i0 + ty * 4 + u) * ldc + j0 + tx * 4] = r;
    }
}

// ---------------------------------------------------------------------------
// Row softmax over 2048-wide rows of g_sim.
// ---------------------------------------------------------------------------
__global__ __launch_bounds__(256)
void softmax_rows(float* __restrict__ sim)
{
    __shared__ float redm[8];
    __shared__ float reds[8];

    const long row = blockIdx.x;
    float* p = sim + row * (long)Nn;
    const int tid  = threadIdx.x;
    const int lane = tid & 31;
    const int wid  = tid >> 5;

    float v[8];
    float m = -1e30f;
    #pragma unroll
    for (int r = 0; r < 8; ++r) {
        v[r] = p[tid + r * 256];
        m = fmaxf(m, v[r]);
    }
    #pragma unroll
    for (int off = 16; off > 0; off >>= 1)
        m = fmaxf(m, __shfl_xor_sync(0xffffffffu, m, off));
    if (lane == 0) redm[wid] = m;
    __syncthreads();
    float bm = redm[0];
    #pragma unroll
    for (int i = 1; i < 8; ++i) bm = fmaxf(bm, redm[i]);

    float s = 0.f;
    #pragma unroll
    for (int r = 0; r < 8; ++r) {
        v[r] = __expf(v[r] - bm);
        s += v[r];
    }
    #pragma unroll
    for (int off = 16; off > 0; off >>= 1)
        s += __shfl_xor_sync(0xffffffffu, s, off);
    if (lane == 0) reds[wid] = s;
    __syncthreads();
    float total = 0.f;
    #pragma unroll
    for (int i = 0; i < 8; ++i) total += reds[i];
    const float inv = 1.0f / total;

    #pragma unroll
    for (int r = 0; r < 8; ++r)
        p[tid + r * 256] = v[r] * inv;
}

// ---------------------------------------------------------------------------
extern "C" void kernel_launch(void* const* d_in, const int* in_sizes, int n_in,
                              void* d_out, int out_size)
{
    const float* x  = (const float*)d_in[0];
    const float* Wq = (const float*)d_in[1];
    const float* Wk = (const float*)d_in[2];
    const float* Wv = (const float*)d_in[3];
    const float* Wo = (const float*)d_in[4];
    float* y = (float*)d_out;

    float *q, *k, *v, *ao, *sim;
    cudaGetSymbolAddress((void**)&q,   g_q);
    cudaGetSymbolAddress((void**)&k,   g_k);
    cudaGetSymbolAddress((void**)&v,   g_v);
    cudaGetSymbolAddress((void**)&ao,  g_ao);
    cudaGetSymbolAddress((void**)&sim, g_sim);

    dim3 blk(256);

    // QKV projections
    dim3 gp(DI / 64, Bsz * (Nn / 16));
    vn_proj<0><<<gp, blk>>>(x, Wq, q);
    vn_proj<0><<<gp, blk>>>(x, Wk, k);
    vn_proj<0><<<gp, blk>>>(x, Wv, v);

    // sim = scale * q k^T   (batched over B*H)
    const float scale = 1.0f / sqrtf((float)Ee);
    dim3 g2(Nn / 64, Nn / 64, Bsz * Hh);
    gemm_tile<true><<<g2, blk>>>(q, k, sim, Ee, Ee, Ee, Nn,
                                 (long)Nn * Ee, (long)Nn * Ee, (long)Nn * Nn, scale);

    // softmax over rows
    softmax_rows<<<Bsz * Hh * Nn, blk>>>(sim);

    // ao = attn @ v
    dim3 g3(Ee / 64, Nn / 64, Bsz * Hh);
    gemm_tile<false><<<g3, blk>>>(sim, v, ao, Nn, Nn, Ee, Ee,
                                  (long)Nn * Nn, (long)Nn * Ee, (long)Nn * Ee, 1.0f);

    // final projection
    dim3 g4(Cc / 64, Bsz * (Nn / 16));
    vn_proj<1><<<g4, blk>>>(ao, Wo, y);
}

// round 3
// speedup vs baseline: 1.9777x; 1.9777x over previous
#include <cuda_runtime.h>
#include <cuda_bf16.h>
#include <math.h>
#include <stdint.h>

#define Bsz 2
#define Nn 2048
#define Cc 256
#define COOR 3
#define Hh 8
#define Dd 64
#define Ee 192   // Dd * COOR
#define DI 512   // Hh * Dd
#define BH 16    // Bsz * Hh

#define LDH 72   // smem tile leading dim in halves (144B rows -> conflict-free ldmatrix)

// ---------------- scratch (device globals; no runtime allocation) ----------
__device__ float g_q[BH * Nn * Ee];
__device__ float g_k[BH * Nn * Ee];
__device__ float g_vt[BH * Ee * Nn];   // transposed: [bh][e][n]
__device__ float g_sim[BH * Nn * Nn];  // 256 MiB
__device__ float g_ao[BH * Nn * Ee];

// ---------------- helpers ---------------------------------------------------
__device__ __forceinline__ uint32_t s2u(const void* p) {
    uint32_t a;
    asm("{ .reg .u64 t; cvta.to.shared.u64 t, %1; cvt.u32.u64 %0, t; }"
        : "=r"(a) : "l"(p));
    return a;
}
__device__ __forceinline__ void ldm4(uint32_t& r0, uint32_t& r1, uint32_t& r2,
                                     uint32_t& r3, uint32_t addr) {
    asm volatile("ldmatrix.sync.aligned.m8n8.x4.shared.b16 {%0,%1,%2,%3}, [%4];"
                 : "=r"(r0), "=r"(r1), "=r"(r2), "=r"(r3) : "r"(addr));
}
__device__ __forceinline__ void mma16816(float* c, const uint32_t* a, const uint32_t* b) {
    asm volatile(
        "mma.sync.aligned.m16n8k16.row.col.f32.bf16.bf16.f32 "
        "{%0,%1,%2,%3},{%4,%5,%6,%7},{%8,%9},{%0,%1,%2,%3};"
        : "+f"(c[0]), "+f"(c[1]), "+f"(c[2]), "+f"(c[3])
        : "r"(a[0]), "r"(a[1]), "r"(a[2]), "r"(a[3]), "r"(b[0]), "r"(b[1]));
}
// split float4 into bf16 hi pair-regs and lo pair-regs
__device__ __forceinline__ void split4(float4 v, uint32_t h[2], uint32_t l[2]) {
    __nv_bfloat16 h0 = __float2bfloat16(v.x), h1 = __float2bfloat16(v.y);
    __nv_bfloat16 h2 = __float2bfloat16(v.z), h3 = __float2bfloat16(v.w);
    __nv_bfloat16 l0 = __float2bfloat16(v.x - __bfloat162float(h0));
    __nv_bfloat16 l1 = __float2bfloat16(v.y - __bfloat162float(h1));
    __nv_bfloat16 l2 = __float2bfloat16(v.z - __bfloat162float(h2));
    __nv_bfloat16 l3 = __float2bfloat16(v.w - __bfloat162float(h3));
    __nv_bfloat162 p;
    p = __nv_bfloat162(h0, h1); h[0] = *(uint32_t*)&p;
    p = __nv_bfloat162(h2, h3); h[1] = *(uint32_t*)&p;
    p = __nv_bfloat162(l0, l1); l[0] = *(uint32_t*)&p;
    p = __nv_bfloat162(l2, l3); l[1] = *(uint32_t*)&p;
}

// ---------------------------------------------------------------------------
// Projections (fp32 SIMT).
// MODE 0: q/k proj -> fp32 [bh][n][e]
// MODE 1: v proj   -> fp32 [bh][e][n]   (transposed for AV B-operand)
// MODE 2: out proj -> fp32 final output
// ---------------------------------------------------------------------------
template<int MODE>
__global__ __launch_bounds__(256)
void vn_proj(const float* __restrict__ in, const float* __restrict__ W,
             float* __restrict__ out)
{
    constexpr int K  = (MODE == 2) ? DI : Cc;
    constexpr int NT = K / 64;

    __shared__ float Wt[64][68];
    __shared__ float Xt[16][Ee];

    const int tid   = threadIdx.x;
    const int o0    = blockIdx.x * 64;
    const int ntile = blockIdx.y % (Nn / 16);
    const int b     = blockIdx.y / (Nn / 16);
    const int n0    = ntile * 16;
    const int n_loc = tid >> 4;
    const int o_grp = tid & 15;

    float acc[4][3] = {};

    for (int t = 0; t < NT; ++t) {
        const int k0 = t * 64;
        #pragma unroll
        for (int j = 0; j < 12; ++j) {
            int l   = tid + j * 256;
            int nl  = l / Ee;
            int idx = l - nl * Ee;
            long base;
            if (MODE != 2)
                base = (((long)b * Nn + (n0 + nl)) * Cc + k0) * COOR;
            else
                base = (((long)b * Hh + t) * Nn + (n0 + nl)) * (long)Ee;
            Xt[nl][idx] = in[base + idx];
        }
        #pragma unroll
        for (int j = 0; j < 16; ++j) {
            int l  = tid + j * 256;
            int kk = l & 63;
            int o  = l >> 6;
            Wt[kk][o] = W[(long)(o0 + o) * K + k0 + kk];
        }
        __syncthreads();
        #pragma unroll
        for (int kk = 0; kk < 64; ++kk) {
            float x0 = Xt[n_loc][kk*3 + 0];
            float x1 = Xt[n_loc][kk*3 + 1];
            float x2 = Xt[n_loc][kk*3 + 2];
            float4 w = *(const float4*)&Wt[kk][o_grp * 4];
            acc[0][0] += w.x * x0; acc[0][1] += w.x * x1; acc[0][2] += w.x * x2;
            acc[1][0] += w.y * x0; acc[1][1] += w.y * x1; acc[1][2] += w.y * x2;
            acc[2][0] += w.z * x0; acc[2][1] += w.z * x1; acc[2][2] += w.z * x2;
            acc[3][0] += w.w * x0; acc[3][1] += w.w * x1; acc[3][2] += w.w * x2;
        }
        __syncthreads();
    }

    const int n = n0 + n_loc;
    #pragma unroll
    for (int u = 0; u < 4; ++u) {
        int o = o0 + o_grp * 4 + u;
        if (MODE == 2) {
            float* dst = &out[(((long)b * Nn + n) * Cc + o) * (long)COOR];
            dst[0] = acc[u][0]; dst[1] = acc[u][1]; dst[2] = acc[u][2];
        } else {
            int h = o >> 6, d = o & 63;
            long bh = b * Hh + h;
            #pragma unroll
            for (int c = 0; c < 3; ++c) {
                long idx;
                if (MODE == 0) idx = (bh * Nn + n) * Ee + d * 3 + c;
                else           idx = (bh * Ee + d * 3 + c) * Nn + n;
                out[idx] = acc[u][c];
            }
        }
    }
}

// ---------------------------------------------------------------------------
// QK^T via HMMA (split bf16): sim = scale * q k^T.
// CTA tile 128x128, K=192 in 3 chunks of 64.  8 warps (2x4), warp tile 64x32.
// ---------------------------------------------------------------------------
__global__ __launch_bounds__(256)
void vn_qk(const float* __restrict__ q, const float* __restrict__ k,
           float* __restrict__ sim, float scale)
{
    extern __shared__ __align__(16) char sm[];
    const int TB = 128 * LDH * 2;          // 18432 bytes per tile
    uint32_t sAh = s2u(sm);
    uint32_t sAl = sAh + TB;
    uint32_t sBh = sAh + 2 * TB;
    uint32_t sBl = sAh + 3 * TB;

    const int tid = threadIdx.x, lane = tid & 31, wid = tid >> 5;
    const int wm = wid >> 2, wn = wid & 3;        // 2 x 4 warp grid
    const int j0 = blockIdx.x * 128, i0 = blockIdx.y * 128, bh = blockIdx.z;

    const float* A = q + ((long)bh * Nn + i0) * Ee;
    const float* B = k + ((long)bh * Nn + j0) * Ee;

    float acc[4][4][4] = {};

    // per-lane ldmatrix address components
    const int lrow = lane & 15;
    const int lcol8 = (lane >> 4) << 3;           // 0 or 8 halves

    for (int ch = 0; ch < 3; ++ch) {
        const int kc = ch * 64;
        // stage A and B chunks (128 x 64 fp32 each), split to bf16 hi/lo
        #pragma unroll
        for (int g = tid; g < 128 * 16; g += 256) {
            int row = g >> 4, c4 = (g & 15) << 2;
            uint32_t h[2], l[2];
            split4(*(const float4*)(A + (long)row * Ee + kc + c4), h, l);
            uint32_t off = (row * LDH + c4) * 2;
            *(uint2*)(sm + (sAh - s2u(sm)) + off) = make_uint2(h[0], h[1]);
            *(uint2*)(sm + (sAl - s2u(sm)) + off) = make_uint2(l[0], l[1]);
            split4(*(const float4*)(B + (long)row * Ee + kc + c4), h, l);
            *(uint2*)(sm + (sBh - s2u(sm)) + off) = make_uint2(h[0], h[1]);
            *(uint2*)(sm + (sBl - s2u(sm)) + off) = make_uint2(l[0], l[1]);
        }
        __syncthreads();

        #pragma unroll
        for (int ks = 0; ks < 4; ++ks) {
            const int kh = ks * 16 + lcol8;        // half col within chunk
            uint32_t ah[4][4], al[4][4];
            #pragma unroll
            for (int mt = 0; mt < 4; ++mt) {
                uint32_t r = (wm * 64 + mt * 16 + lrow) * LDH + kh;
                ldm4(ah[mt][0], ah[mt][1], ah[mt][2], ah[mt][3], sAh + r * 2);
                ldm4(al[mt][0], al[mt][1], al[mt][2], al[mt][3], sAl + r * 2);
            }
            uint32_t bhf[4][2], blf[4][2];
            #pragma unroll
            for (int g = 0; g < 2; ++g) {
                uint32_t r = (wn * 32 + g * 16 + lrow) * LDH + kh;
                uint32_t r0, r1, r2, r3;
                ldm4(r0, r1, r2, r3, sBh + r * 2);
                bhf[g*2][0] = r0; bhf[g*2][1] = r2;
                bhf[g*2+1][0] = r1; bhf[g*2+1][1] = r3;
                ldm4(r0, r1, r2, r3, sBl + r * 2);
                blf[g*2][0] = r0; blf[g*2][1] = r2;
                blf[g*2+1][0] = r1; blf[g*2+1][1] = r3;
            }
            #pragma unroll
            for (int mt = 0; mt < 4; ++mt)
                #pragma unroll
                for (int nt = 0; nt < 4; ++nt) {
                    mma16816(acc[mt][nt], ah[mt], bhf[nt]);
                    mma16816(acc[mt][nt], ah[mt], blf[nt]);
                    mma16816(acc[mt][nt], al[mt], bhf[nt]);
                }
        }
        __syncthreads();
    }

    // epilogue
    #pragma unroll
    for (int mt = 0; mt < 4; ++mt) {
        #pragma unroll
        for (int nt = 0; nt < 4; ++nt) {
            int row = i0 + wm * 64 + mt * 16 + (lane >> 2);
            int col = j0 + wn * 32 + nt * 8 + (lane & 3) * 2;
            float* base = sim + ((long)bh * Nn + row) * Nn + col;
            *(float2*)base = make_float2(acc[mt][nt][0] * scale, acc[mt][nt][1] * scale);
            *(float2*)(base + 8L * Nn) =
                make_float2(acc[mt][nt][2] * scale, acc[mt][nt][3] * scale);
        }
    }
}

// ---------------------------------------------------------------------------
// AV via HMMA (split bf16): ao[i][e] = sum_j attn[i][j] vt[e][j].
// CTA tile 64x192, K=2048 in 32 chunks of 64.  8 warps (2x4), warp tile 32x48.
// ---------------------------------------------------------------------------
__global__ __launch_bounds__(256)
void vn_av(const float* __restrict__ sim, const float* __restrict__ vt,
           float* __restrict__ ao)
{
    extern __shared__ __align__(16) char sm[];
    const int TA = 64 * LDH * 2;           //  9216 bytes
    const int TBB = 192 * LDH * 2;         // 27648 bytes
    uint32_t sAh = s2u(sm);
    uint32_t sAl = sAh + TA;
    uint32_t sBh = sAh + 2 * TA;
    uint32_t sBl = sAh + 2 * TA + TBB;

    const int tid = threadIdx.x, lane = tid & 31, wid = tid >> 5;
    const int wm = wid >> 2, wn = wid & 3;        // 2 x 4
    const int i0 = blockIdx.x * 64, bh = blockIdx.y;

    const float* A = sim + ((long)bh * Nn + i0) * Nn;
    const float* B = vt + (long)bh * Ee * Nn;

    float acc[2][6][4] = {};

    const int lrow = lane & 15;
    const int lcol8 = (lane >> 4) << 3;

    for (int ch = 0; ch < 32; ++ch) {
        const int jc = ch * 64;
        #pragma unroll
        for (int g = tid; g < 64 * 16; g += 256) {
            int row = g >> 4, c4 = (g & 15) << 2;
            uint32_t h[2], l[2];
            split4(*(const float4*)(A + (long)row * Nn + jc + c4), h, l);
            uint32_t off = (row * LDH + c4) * 2;
            *(uint2*)(sm + (sAh - s2u(sm)) + off) = make_uint2(h[0], h[1]);
            *(uint2*)(sm + (sAl - s2u(sm)) + off) = make_uint2(l[0], l[1]);
        }
        #pragma unroll
        for (int g = tid; g < 192 * 16; g += 256) {
            int row = g >> 4, c4 = (g & 15) << 2;
            uint32_t h[2], l[2];
            split4(*(const float4*)(B + (long)row * Nn + jc + c4), h, l);
            uint32_t off = (row * LDH + c4) * 2;
            *(uint2*)(sm + (sBh - s2u(sm)) + off) = make_uint2(h[0], h[1]);
            *(uint2*)(sm + (sBl - s2u(sm)) + off) = make_uint2(l[0], l[1]);
        }
        __syncthreads();

        #pragma unroll
        for (int ks = 0; ks < 4; ++ks) {
            const int kh = ks * 16 + lcol8;
            uint32_t ah[2][4], al[2][4];
            #pragma unroll
            for (int mt = 0; mt < 2; ++mt) {
                uint32_t r = (wm * 32 + mt * 16 + lrow) * LDH + kh;
                ldm4(ah[mt][0], ah[mt][1], ah[mt][2], ah[mt][3], sAh + r * 2);
                ldm4(al[mt][0], al[mt][1], al[mt][2], al[mt][3], sAl + r * 2);
            }
            uint32_t bhf[6][2], blf[6][2];
            #pragma unroll
            for (int g = 0; g < 3; ++g) {
                uint32_t r = (wn * 48 + g * 16 + lrow) * LDH + kh;
                uint32_t r0, r1, r2, r3;
                ldm4(r0, r1, r2, r3, sBh + r * 2);
                bhf[g*2][0] = r0; bhf[g*2][1] = r2;
                bhf[g*2+1][0] = r1; bhf[g*2+1][1] = r3;
                ldm4(r0, r1, r2, r3, sBl + r * 2);
                blf[g*2][0] = r0; blf[g*2][1] = r2;
                blf[g*2+1][0] = r1; blf[g*2+1][1] = r3;
            }
            #pragma unroll
            for (int mt = 0; mt < 2; ++mt)
                #pragma unroll
                for (int nt = 0; nt < 6; ++nt) {
                    mma16816(acc[mt][nt], ah[mt], bhf[nt]);
                    mma16816(acc[mt][nt], ah[mt], blf[nt]);
                    mma16816(acc[mt][nt], al[mt], bhf[nt]);
                }
        }
        __syncthreads();
    }

    #pragma unroll
    for (int mt = 0; mt < 2; ++mt) {
        #pragma unroll
        for (int nt = 0; nt < 6; ++nt) {
            int row = i0 + wm * 32 + mt * 16 + (lane >> 2);
            int col = wn * 48 + nt * 8 + (lane & 3) * 2;
            float* base = ao + ((long)bh * Nn + row) * Ee + col;
            *(float2*)base = make_float2(acc[mt][nt][0], acc[mt][nt][1]);
            *(float2*)(base + 8L * Ee) = make_float2(acc[mt][nt][2], acc[mt][nt][3]);
        }
    }
}

// ---------------------------------------------------------------------------
// Row softmax over 2048-wide rows of g_sim (in place).
// ---------------------------------------------------------------------------
__global__ __launch_bounds__(256)
void softmax_rows(float* __restrict__ sim)
{
    __shared__ float redm[8];
    __shared__ float reds[8];

    const long row = blockIdx.x;
    float* p = sim + row * (long)Nn;
    const int tid  = threadIdx.x;
    const int lane = tid & 31;
    const int wid  = tid >> 5;

    float v[8];
    float m = -1e30f;
    #pragma unroll
    for (int r = 0; r < 8; ++r) {
        v[r] = p[tid + r * 256];
        m = fmaxf(m, v[r]);
    }
    #pragma unroll
    for (int off = 16; off > 0; off >>= 1)
        m = fmaxf(m, __shfl_xor_sync(0xffffffffu, m, off));
    if (lane == 0) redm[wid] = m;
    __syncthreads();
    float bm = redm[0];
    #pragma unroll
    for (int i = 1; i < 8; ++i) bm = fmaxf(bm, redm[i]);

    float s = 0.f;
    #pragma unroll
    for (int r = 0; r < 8; ++r) {
        v[r] = __expf(v[r] - bm);
        s += v[r];
    }
    #pragma unroll
    for (int off = 16; off > 0; off >>= 1)
        s += __shfl_xor_sync(0xffffffffu, s, off);
    if (lane == 0) reds[wid] = s;
    __syncthreads();
    float total = 0.f;
    #pragma unroll
    for (int i = 0; i < 8; ++i) total += reds[i];
    const float inv = 1.0f / total;

    #pragma unroll
    for (int r = 0; r < 8; ++r)
        p[tid + r * 256] = v[r] * inv;
}

// ---------------------------------------------------------------------------
extern "C" void kernel_launch(void* const* d_in, const int* in_sizes, int n_in,
                              void* d_out, int out_size)
{
    const float* x  = (const float*)d_in[0];
    const float* Wq = (const float*)d_in[1];
    const float* Wk = (const float*)d_in[2];
    const float* Wv = (const float*)d_in[3];
    const float* Wo = (const float*)d_in[4];
    float* y = (float*)d_out;

    float *q, *k, *vt, *sim, *ao;
    cudaGetSymbolAddress((void**)&q,   g_q);
    cudaGetSymbolAddress((void**)&k,   g_k);
    cudaGetSymbolAddress((void**)&vt,  g_vt);
    cudaGetSymbolAddress((void**)&sim, g_sim);
    cudaGetSymbolAddress((void**)&ao,  g_ao);

    const int QK_SMEM = 4 * (128 * LDH * 2);                       // 73728
    const int AV_SMEM = 2 * (64 * LDH * 2) + 2 * (192 * LDH * 2);  // 73728
    cudaFuncSetAttribute(vn_qk, cudaFuncAttributeMaxDynamicSharedMemorySize, QK_SMEM);
    cudaFuncSetAttribute(vn_av, cudaFuncAttributeMaxDynamicSharedMemorySize, AV_SMEM);

    dim3 blk(256);

    // projections
    dim3 gp(DI / 64, Bsz * (Nn / 16));
    vn_proj<0><<<gp, blk>>>(x, Wq, q);
    vn_proj<0><<<gp, blk>>>(x, Wk, k);
    vn_proj<1><<<gp, blk>>>(x, Wv, vt);

    // sim = scale * q k^T
    const float scale = 1.0f / sqrtf((float)Ee);
    dim3 g2(Nn / 128, Nn / 128, BH);
    vn_qk<<<g2, blk, QK_SMEM>>>(q, k, sim, scale);

    // softmax in place
    softmax_rows<<<BH * Nn, blk>>>(sim);

    // ao = attn @ v
    dim3 g3(Nn / 64, BH);
    vn_av<<<g3, blk, AV_SMEM>>>(sim, vt, ao);

    // final projection
    dim3 g4(Cc / 64, Bsz * (Nn / 16));
    vn_proj<2><<<g4, blk>>>(ao, Wo, y);
}